// round 15
// baseline (speedup 1.0000x reference)
#include <cuda_runtime.h>
#include <cuda_fp16.h>
#include <cstdint>

#define NL  2048
#define NE  256
#define NH  8
#define NHW 32
#define NB  2

// Scratch (static device globals -- no runtime allocation)
__device__ float   g_Q   [NB*NH*NL*NHW];   // [bh][l][d] fp32 (pre-scaled)
__device__ float   g_K   [NB*NH*NL*NHW];   // [bh][l][d] tf32-hi
__device__ float   g_Klo [NB*NH*NL*NHW];   // [bh][l][d] tf32-lo
__device__ float   g_Vt  [NB*NH*NHW*NL];   // [bh][d][l] tf32-hi (transposed)
__device__ float   g_Vtlo[NB*NH*NHW*NL];   // [bh][d][l] tf32-lo
__device__ float   g_Y   [NB*NL*NE];
__device__ __half2 g_Bt  [(size_t)NB*NH*NL*NL/2]; // bias^T [b][h][q][k] fp16

typedef unsigned long long u64;

static __device__ __forceinline__ u64 pack2(float lo, float hi) {
    u64 r; asm("mov.b64 %0, {%1,%2};" : "=l"(r) : "f"(lo), "f"(hi)); return r;
}
static __device__ __forceinline__ void unpack2(u64 a, float& lo, float& hi) {
    asm("mov.b64 {%0,%1}, %2;" : "=f"(lo), "=f"(hi) : "l"(a));
}
static __device__ __forceinline__ void fma2(u64& acc, u64 a, u64 b) {
    asm("fma.rn.f32x2 %0, %1, %2, %3;" : "=l"(acc) : "l"(a), "l"(b), "l"(acc));
}
static __device__ __forceinline__ void cp16(void* dst, const void* src) {
    unsigned d = (unsigned)__cvta_generic_to_shared(dst);
    asm volatile("cp.async.cg.shared.global [%0], [%1], 16;" :: "r"(d), "l"(src));
}
static __device__ __forceinline__ void cp4(void* dst, const void* src) {
    unsigned d = (unsigned)__cvta_generic_to_shared(dst);
    asm volatile("cp.async.ca.shared.global [%0], [%1], 4;" :: "r"(d), "l"(src));
}
static __device__ __forceinline__ void cp_commit() {
    asm volatile("cp.async.commit_group;");
}
static __device__ __forceinline__ void cp_wait1() {
    asm volatile("cp.async.wait_group 1;");
}
static __device__ __forceinline__ void cp_wait0() {
    asm volatile("cp.async.wait_group 0;");
}
static __device__ __forceinline__ uint32_t smem_u32(const void* p) {
    return (uint32_t)__cvta_generic_to_shared(p);
}
static __device__ __forceinline__ uint32_t tf32_rna_u(float x) {
    uint32_t r; asm("cvt.rna.tf32.f32 %0, %1;" : "=r"(r) : "f"(x)); return r;
}
static __device__ __forceinline__ float tf32_rna_f(float x) {
    return __uint_as_float(tf32_rna_u(x));
}
// tf32 mma m16n8k8, fp32 accumulate (arch-portable tensor path)
static __device__ __forceinline__ void mma_tf32(float* c, const uint32_t* a,
                                                uint32_t b0, uint32_t b1) {
    asm volatile(
        "mma.sync.aligned.m16n8k8.row.col.f32.tf32.tf32.f32 "
        "{%0,%1,%2,%3}, {%4,%5,%6,%7}, {%8,%9}, {%0,%1,%2,%3};"
        : "+f"(c[0]), "+f"(c[1]), "+f"(c[2]), "+f"(c[3])
        : "r"(a[0]), "r"(a[1]), "r"(a[2]), "r"(a[3]), "r"(b0), "r"(b1));
}
// ldmatrix x4 (b16 view of b32 tiles)
static __device__ __forceinline__ void ldsm4(uint32_t* r, uint32_t addr) {
    asm volatile("ldmatrix.sync.aligned.m8n8.x4.shared.b16 {%0,%1,%2,%3}, [%4];"
        : "=r"(r[0]), "=r"(r[1]), "=r"(r[2]), "=r"(r[3]) : "r"(addr));
}

// ---------------------------------------------------------------------------
// GEMM (NT): C[m][n] = sum_k A[m][k]*W[n][k], K=256. 128x64 tile, 256 thr.
// 2-stage cp.async chunk pipeline (copy c+1 overlaps compute c).
// EPI 0: Q fp32 (scaled); K hi/lo [bh][l][d]; V hi/lo transposed [bh][d][l].
// EPI 1: out + bias.
// smem (dynamic, floats): As 2x4224 @0, Bs 2x2176 @8448  => 51200 bytes
// ---------------------------------------------------------------------------
#define GSM_BYTES 51200

template<int EPI>
__global__ __launch_bounds__(256) void gemm_nt(const float* __restrict__ A,
                                               const float* __restrict__ W,
                                               const float* __restrict__ bo,
                                               float* __restrict__ out)
{
    extern __shared__ __align__(16) float gsm[];
    const int tid = threadIdx.x;
    const int tx = tid & 15, ty = tid >> 4;
    const int m0 = blockIdx.x * 128, n0 = blockIdx.y * 64;

    auto stage = [&](int slot, int kc) {
        float* As = gsm + slot * 4224;
        float* Bs = gsm + 8448 + slot * 2176;
        #pragma unroll
        for (int i = 0; i < 4; i++) {
            int idx = tid + i * 256;
            int row = idx >> 3, c4 = (idx & 7) << 2;
            const float* src = A + (size_t)(m0 + row) * 256 + kc + c4;
            #pragma unroll
            for (int j = 0; j < 4; j++)
                cp4(As + (c4 + j) * 132 + row, src + j);
        }
        #pragma unroll
        for (int i = 0; i < 2; i++) {
            int idx = tid + i * 256;
            int row = idx >> 3, c4 = (idx & 7) << 2;
            const float* src = W + (size_t)(n0 + row) * 256 + kc + c4;
            #pragma unroll
            for (int j = 0; j < 4; j++)
                cp4(Bs + (c4 + j) * 68 + row, src + j);
        }
    };

    u64 acc[4][4];
    #pragma unroll
    for (int p = 0; p < 4; p++)
        #pragma unroll
        for (int j = 0; j < 4; j++) acc[p][j] = 0ULL;

    stage(0, 0);
    cp_commit();

    for (int c = 0; c < 8; c++) {
        cp_wait0();
        __syncthreads();
        if (c < 7) stage((c + 1) & 1, (c + 1) * 32);
        cp_commit();

        const float* As = gsm + (c & 1) * 4224;
        const float* Bs = gsm + 8448 + (c & 1) * 2176;
        #pragma unroll
        for (int k = 0; k < 32; k++) {
            ulonglong2 aA = *(const ulonglong2*)&As[k * 132 + ty * 8];
            ulonglong2 aB = *(const ulonglong2*)&As[k * 132 + ty * 8 + 4];
            float4 b4 = *(const float4*)&Bs[k * 68 + tx * 4];
            u64 bb;
            bb = pack2(b4.x, b4.x);
            fma2(acc[0][0], aA.x, bb); fma2(acc[1][0], aA.y, bb);
            fma2(acc[2][0], aB.x, bb); fma2(acc[3][0], aB.y, bb);
            bb = pack2(b4.y, b4.y);
            fma2(acc[0][1], aA.x, bb); fma2(acc[1][1], aA.y, bb);
            fma2(acc[2][1], aB.x, bb); fma2(acc[3][1], aB.y, bb);
            bb = pack2(b4.z, b4.z);
            fma2(acc[0][2], aA.x, bb); fma2(acc[1][2], aA.y, bb);
            fma2(acc[2][2], aB.x, bb); fma2(acc[3][2], aB.y, bb);
            bb = pack2(b4.w, b4.w);
            fma2(acc[0][3], aA.x, bb); fma2(acc[1][3], aA.y, bb);
            fma2(acc[2][3], aB.x, bb); fma2(acc[3][3], aB.y, bb);
        }
    }

    #pragma unroll
    for (int p = 0; p < 4; p++) {
        int m = m0 + ty * 8 + 2 * p;
        #pragma unroll
        for (int j = 0; j < 4; j++) {
            float v0, v1; unpack2(acc[p][j], v0, v1);
            int n = n0 + tx * 4 + j;
            if (EPI == 0) {
                int hh = n / 96, rem = n % 96;
                int part = rem >> 5, c = rem & 31;
                int bb_ = m >> 11, l = m & 2047;
                int bh = bb_ * NH + hh;
                if (part == 0) {
                    size_t base = ((size_t)bh * NL + l) * NHW + c;
                    g_Q[base]       = v0 * 0.17677669529663687f;
                    g_Q[base + NHW] = v1 * 0.17677669529663687f;
                } else {
                    float h0 = tf32_rna_f(v0), h1 = tf32_rna_f(v1);
                    float l0 = tf32_rna_f(v0 - h0), l1 = tf32_rna_f(v1 - h1);
                    if (part == 1) {
                        size_t base = ((size_t)bh * NL + l) * NHW + c;
                        g_K  [base] = h0; g_K  [base + NHW] = h1;
                        g_Klo[base] = l0; g_Klo[base + NHW] = l1;
                    } else {
                        size_t base = ((size_t)bh * NHW + c) * NL + l;
                        g_Vt  [base] = h0; g_Vt  [base + 1] = h1;
                        g_Vtlo[base] = l0; g_Vtlo[base + 1] = l1;
                    }
                }
            } else {
                float bias_ = bo[n];
                out[(size_t)m * NE + n]       = v0 + bias_;
                out[(size_t)(m + 1) * NE + n] = v1 + bias_;
            }
        }
    }
}

// ---------------------------------------------------------------------------
// bias transpose: [b][q][k][h] fp32 -> [b][h][q][k] fp16 (HBM-bound)
// ---------------------------------------------------------------------------
__global__ __launch_bounds__(256) void bias_t(const float* __restrict__ bias)
{
    size_t idx = (size_t)blockIdx.x * 256 + threadIdx.x;   // over NB*NL*(NL/2)
    int k2 = idx & 1023;
    size_t rest = idx >> 10;
    int q = rest & 2047;
    int b = (int)(rest >> 11);
    const float4* src = (const float4*)(bias + (((size_t)(b * NL + q)) * NL + 2 * k2) * NH);
    float4 a0 = src[0], a1 = src[1], a2 = src[2], a3 = src[3];
    float f[16];
    *(float4*)&f[0]  = a0; *(float4*)&f[4]  = a1;
    *(float4*)&f[8]  = a2; *(float4*)&f[12] = a3;
    #pragma unroll
    for (int h = 0; h < NH; h++)
        g_Bt[((size_t)(b * NH + h) * NL + q) * (NL / 2) + k2] =
            __floats2half2_rn(f[h], f[8 + h]);
}

// ---------------------------------------------------------------------------
// Split-precision tf32 mma.sync attention, ldmatrix fragments, 3-stage
// cp.async pipeline with ONE barrier per tile, P overlaid on dead Q region.
// CTA = (b,h,128q), 8 warps x 16q, k-tile 32, 2 CTAs/SM.
// ---------------------------------------------------------------------------
#define QP_OFF  0          // Q (prologue) then P; 128 x 144B = 18432
#define KH_OFF  18432      // 3 stages x 4608
#define KL_OFF  32256
#define VH_OFF  46080
#define VL_OFF  59904
#define B_OFF   73728      // 3 stages x 10240
#define SM_TOT  104448
#define B_PITCH 40         // halves per bias row (80 bytes)

__global__ __launch_bounds__(256, 2) void attn_mma()
{
    extern __shared__ __align__(16) char smem[];
    const int tid = threadIdx.x, lane = tid & 31, wid = tid >> 5;
    const int g = lane >> 2, tg = lane & 3;
    const int q0 = blockIdx.x * 128;
    const int bh = blockIdx.y;
    const int b  = bh >> 3, h = bh & 7;

    const __half* btp = (const __half*)g_Bt;

    const int krow = tid >> 3, kch = tid & 7;
    auto stage = [&](int slot, int k0) {
        cp16(smem + KH_OFF + slot * 4608 + krow * 144 + kch * 16,
             g_K   + ((size_t)bh * NL + k0 + krow) * NHW + kch * 4);
        cp16(smem + KL_OFF + slot * 4608 + krow * 144 + kch * 16,
             g_Klo + ((size_t)bh * NL + k0 + krow) * NHW + kch * 4);
        cp16(smem + VH_OFF + slot * 4608 + krow * 144 + kch * 16,
             g_Vt   + ((size_t)bh * NHW + krow) * NL + k0 + kch * 4);
        cp16(smem + VL_OFF + slot * 4608 + krow * 144 + kch * 16,
             g_Vtlo + ((size_t)bh * NHW + krow) * NL + k0 + kch * 4);
        #pragma unroll
        for (int i = 0; i < 2; i++) {
            int idx = i * 256 + tid, row = idx >> 2, ch = idx & 3;
            cp16(smem + B_OFF + slot * 10240 + row * 80 + ch * 16,
                 btp + ((size_t)bh * NL + q0 + row) * NL + k0 + ch * 8);
        }
    };

    // prologue: Q + tile0 (group 0), tile1 (group 1)
    #pragma unroll
    for (int i = 0; i < 4; i++) {
        int idx = i * 256 + tid, row = idx >> 3, ch = idx & 7;
        cp16(smem + QP_OFF + row * 144 + ch * 16,
             g_Q + ((size_t)bh * NL + q0 + row) * NHW + ch * 4);
    }
    stage(0, 0);
    cp_commit();
    stage(1, 32);
    cp_commit();
    cp_wait1();
    __syncthreads();

    // preload split Q fragments (A: m16k8 tf32) for this warp's 16 q-rows
    uint32_t aqh[4][4], aql[4][4];
    {
        const float* qb = (const float*)(smem + QP_OFF) + (wid * 16 + g) * 36;
        #pragma unroll
        for (int kk = 0; kk < 4; kk++) {
            float q00 = qb[kk * 8 + tg];
            float q01 = qb[8 * 36 + kk * 8 + tg];
            float q10 = qb[kk * 8 + tg + 4];
            float q11 = qb[8 * 36 + kk * 8 + tg + 4];
            float h00 = tf32_rna_f(q00), h01 = tf32_rna_f(q01);
            float h10 = tf32_rna_f(q10), h11 = tf32_rna_f(q11);
            aqh[kk][0] = __float_as_uint(h00);
            aqh[kk][1] = __float_as_uint(h01);
            aqh[kk][2] = __float_as_uint(h10);
            aqh[kk][3] = __float_as_uint(h11);
            aql[kk][0] = tf32_rna_u(q00 - h00);
            aql[kk][1] = tf32_rna_u(q01 - h01);
            aql[kk][2] = tf32_rna_u(q10 - h10);
            aql[kk][3] = tf32_rna_u(q11 - h11);
        }
    }

    // ldmatrix per-lane address invariants
    const uint32_t sb = smem_u32(smem);
    const int r7 = lane & 7, h8 = (lane >> 3) & 1, hi16 = lane >> 4;
    const uint32_t inv_b = r7 * 144 + h8 * 16 + hi16 * 1152;   // B-frags (K/V)
    const uint32_t inv_a = r7 * 144 + h8 * 1152 + hi16 * 16;   // A-frags (P)
    const uint32_t aKH = sb + KH_OFF + inv_b;
    const uint32_t aKL = sb + KL_OFF + inv_b;
    const uint32_t aVH = sb + VH_OFF + inv_b;
    const uint32_t aVL = sb + VL_OFF + inv_b;
    const uint32_t aP  = sb + QP_OFF + wid * 2304 + inv_a;

    float co[4][4];
    #pragma unroll
    for (int n = 0; n < 4; n++)
        #pragma unroll
        for (int j = 0; j < 4; j++) co[n][j] = 0.f;
    float lsum0 = 0.f, lsum1 = 0.f;

    float* Ps = (float*)(smem + QP_OFF) + wid * 16 * 36;

    int sr = 0, sw = 2;
    for (int t = 0; t < 64; t++) {
        // wait tile t complete; barrier; then refill slot read 2 iters ago
        cp_wait1();
        __syncthreads();
        if (t + 2 < 64) stage(sw, (t + 2) * 32);
        cp_commit();

        const uint32_t so = sr * 4608;

        // ---- S = Q @ K^T, split-precision 3-MMA
        float c[4][4];
        #pragma unroll
        for (int n = 0; n < 4; n++)
            #pragma unroll
            for (int j = 0; j < 4; j++) c[n][j] = 0.f;
        #pragma unroll
        for (int kk = 0; kk < 4; kk++) {
            uint32_t bhf[8], blf[8];
            ldsm4(bhf,     aKH + so + kk * 32);
            ldsm4(bhf + 4, aKH + so + kk * 32 + 2304);
            ldsm4(blf,     aKL + so + kk * 32);
            ldsm4(blf + 4, aKL + so + kk * 32 + 2304);
            #pragma unroll
            for (int n = 0; n < 4; n++) {
                mma_tf32(c[n], aqh[kk], bhf[2 * n], bhf[2 * n + 1]);
                mma_tf32(c[n], aql[kk], bhf[2 * n], bhf[2 * n + 1]);
                mma_tf32(c[n], aqh[kk], blf[2 * n], blf[2 * n + 1]);
            }
        }

        // ---- softmax (no max subtraction; scores bounded), P rounded rna
        const __half* brow = (const __half*)(smem + B_OFF + sr * 10240)
                           + (wid * 16 + g) * B_PITCH;
        #pragma unroll
        for (int n = 0; n < 4; n++) {
            float2 f0 = __half22float2(*(const __half2*)(brow + n * 8 + 2 * tg));
            float2 f1 = __half22float2(*(const __half2*)(brow + 8 * B_PITCH + n * 8 + 2 * tg));
            float p0 = __uint_as_float(tf32_rna_u(__expf(c[n][0] + f0.x)));
            float p1 = __uint_as_float(tf32_rna_u(__expf(c[n][1] + f0.y)));
            float p2 = __uint_as_float(tf32_rna_u(__expf(c[n][2] + f1.x)));
            float p3 = __uint_as_float(tf32_rna_u(__expf(c[n][3] + f1.y)));
            lsum0 += p0 + p1; lsum1 += p2 + p3;
            *(float2*)(Ps + g * 36 + n * 8 + 2 * tg)       = make_float2(p0, p1);
            *(float2*)(Ps + (g + 8) * 36 + n * 8 + 2 * tg) = make_float2(p2, p3);
        }
        __syncwarp();

        // ---- O += P @ (V_hi + V_lo)
        #pragma unroll
        for (int kk = 0; kk < 4; kk++) {
            uint32_t pa[4], vhf[8], vlf[8];
            ldsm4(pa, aP + kk * 32);
            ldsm4(vhf,     aVH + so + kk * 32);
            ldsm4(vhf + 4, aVH + so + kk * 32 + 2304);
            ldsm4(vlf,     aVL + so + kk * 32);
            ldsm4(vlf + 4, aVL + so + kk * 32 + 2304);
            #pragma unroll
            for (int n = 0; n < 4; n++) {
                mma_tf32(co[n], pa, vhf[2 * n], vhf[2 * n + 1]);
                mma_tf32(co[n], pa, vlf[2 * n], vlf[2 * n + 1]);
            }
        }

        sr = (sr == 2) ? 0 : sr + 1;
        sw = (sw == 2) ? 0 : sw + 1;
    }

    // ---- epilogue: row sums live on 4 lanes (same g, tg=0..3) -> 2 shuffles
    #pragma unroll
    for (int off = 1; off <= 2; off <<= 1) {
        lsum0 += __shfl_xor_sync(0xffffffffu, lsum0, off);
        lsum1 += __shfl_xor_sync(0xffffffffu, lsum1, off);
    }
    float inv0 = 1.0f / lsum0, inv1 = 1.0f / lsum1;
    int q = q0 + wid * 16 + g;
    float* y0 = g_Y + ((size_t)(b * NL + q)) * NE + h * NHW;
    #pragma unroll
    for (int n = 0; n < 4; n++) {
        *(float2*)(y0 + n * 8 + 2 * tg) =
            make_float2(co[n][0] * inv0, co[n][1] * inv0);
        *(float2*)(y0 + 8 * NE + n * 8 + 2 * tg) =
            make_float2(co[n][2] * inv1, co[n][3] * inv1);
    }
}

// ---------------------------------------------------------------------------
extern "C" void kernel_launch(void* const* d_in, const int* in_sizes, int n_in,
                              void* d_out, int out_size)
{
    const float* x    = (const float*)d_in[0];
    const float* bias = (const float*)d_in[1];
    const float* Wp   = (const float*)d_in[2];
    const float* Wo   = (const float*)d_in[3];
    const float* bo   = (const float*)d_in[4];
    float* out = (float*)d_out;

    float* yptr;
    cudaGetSymbolAddress((void**)&yptr, g_Y);

    cudaFuncSetAttribute(attn_mma, cudaFuncAttributeMaxDynamicSharedMemorySize,
                         SM_TOT);
    cudaFuncSetAttribute(gemm_nt<0>, cudaFuncAttributeMaxDynamicSharedMemorySize,
                         GSM_BYTES);
    cudaFuncSetAttribute(gemm_nt<1>, cudaFuncAttributeMaxDynamicSharedMemorySize,
                         GSM_BYTES);

    gemm_nt<0><<<dim3(32, 12), 256, GSM_BYTES>>>(x, Wp, nullptr, nullptr);
    bias_t<<<(NB * NL * (NL / 2)) / 256, 256>>>(bias);
    attn_mma<<<dim3(NL / 128, NB * NH), 256, SM_TOT>>>();
    gemm_nt<1><<<dim3(32, 4), 256, GSM_BYTES>>>(yptr, Wo, bo, out);
}

// round 16
// speedup vs baseline: 1.2097x; 1.2097x over previous
#include <cuda_runtime.h>
#include <cuda_fp16.h>
#include <cstdint>

#define NL  2048
#define NE  256
#define NH  8
#define NHW 32
#define NB  2

// Scratch (static device globals -- no runtime allocation)
__device__ float   g_Q   [NB*NH*NL*NHW];   // [bh][l][d] fp32 (pre-scaled)
__device__ float   g_K   [NB*NH*NL*NHW];   // [bh][l][d] tf32-hi
__device__ float   g_Klo [NB*NH*NL*NHW];   // [bh][l][d] tf32-lo
__device__ float   g_Vt  [NB*NH*NHW*NL];   // [bh][d][l] tf32 (rna)
__device__ float   g_Y   [NB*NL*NE];
__device__ __half2 g_Bt  [(size_t)NB*NH*NL*NL/2]; // bias^T [b][h][q][k] fp16
__device__ float   g_Wph [768*256];        // W_proj tf32-hi
__device__ float   g_Wpl [768*256];        // W_proj tf32-lo
__device__ float   g_Woh [256*256];        // W_o tf32-hi
__device__ float   g_Wol [256*256];        // W_o tf32-lo

typedef unsigned long long u64;

static __device__ __forceinline__ void cp16(void* dst, const void* src) {
    unsigned d = (unsigned)__cvta_generic_to_shared(dst);
    asm volatile("cp.async.cg.shared.global [%0], [%1], 16;" :: "r"(d), "l"(src));
}
static __device__ __forceinline__ void cp_commit() {
    asm volatile("cp.async.commit_group;");
}
static __device__ __forceinline__ void cp_wait1() {
    asm volatile("cp.async.wait_group 1;");
}
static __device__ __forceinline__ void cp_wait0() {
    asm volatile("cp.async.wait_group 0;");
}
static __device__ __forceinline__ uint32_t smem_u32(const void* p) {
    return (uint32_t)__cvta_generic_to_shared(p);
}
static __device__ __forceinline__ uint32_t tf32_rna_u(float x) {
    uint32_t r; asm("cvt.rna.tf32.f32 %0, %1;" : "=r"(r) : "f"(x)); return r;
}
static __device__ __forceinline__ float tf32_rna_f(float x) {
    return __uint_as_float(tf32_rna_u(x));
}
// tf32 mma m16n8k8, fp32 accumulate (arch-portable tensor path)
static __device__ __forceinline__ void mma_tf32(float* c, const uint32_t* a,
                                                uint32_t b0, uint32_t b1) {
    asm volatile(
        "mma.sync.aligned.m16n8k8.row.col.f32.tf32.tf32.f32 "
        "{%0,%1,%2,%3}, {%4,%5,%6,%7}, {%8,%9}, {%0,%1,%2,%3};"
        : "+f"(c[0]), "+f"(c[1]), "+f"(c[2]), "+f"(c[3])
        : "r"(a[0]), "r"(a[1]), "r"(a[2]), "r"(a[3]), "r"(b0), "r"(b1));
}
// ldmatrix x4 (b16 view of b32 tiles)
static __device__ __forceinline__ void ldsm4(uint32_t* r, uint32_t addr) {
    asm volatile("ldmatrix.sync.aligned.m8n8.x4.shared.b16 {%0,%1,%2,%3}, [%4];"
        : "=r"(r[0]), "=r"(r[1]), "=r"(r[2]), "=r"(r[3]) : "r"(addr));
}

// ---------------------------------------------------------------------------
// W pre-split: Wp (768x256) and Wo (256x256) -> tf32 hi/lo pairs in gmem
// ---------------------------------------------------------------------------
__global__ __launch_bounds__(256) void split_w(const float* __restrict__ Wp,
                                               const float* __restrict__ Wo)
{
    int idx = blockIdx.x * 256 + threadIdx.x;      // over 1024*256
    if (idx < 768 * 256) {
        float v = Wp[idx];
        float h = tf32_rna_f(v);
        g_Wph[idx] = h;
        g_Wpl[idx] = tf32_rna_f(v - h);
    } else {
        int j = idx - 768 * 256;
        float v = Wo[j];
        float h = tf32_rna_f(v);
        g_Woh[j] = h;
        g_Wol[j] = tf32_rna_f(v - h);
    }
}

// ---------------------------------------------------------------------------
// Tensor-core GEMM (NT): C[m][n] = sum_k A[m][k]*W[n][k], K=256.
// 128m x 64n CTA tile, 8 warps x 16m. Split-precision 3-MMA (A split in regs,
// W pre-split in gmem) => fp32-equivalent accuracy. 2-stage cp.async pipeline.
// EPI 0: scatter Q (scaled fp32) / K hi,lo / Vt (rna).  EPI 1: out + bias.
// smem: A 2x18432 @0, Wh 2x9216 @36864, Wl 2x9216 @55296 => 73728 B
// ---------------------------------------------------------------------------
#define GA_OFF  0
#define GWH_OFF 36864
#define GWL_OFF 55296
#define GSM_BYTES 73728

template<int EPI>
__global__ __launch_bounds__(256, 2) void gemm_mma(const float* __restrict__ A,
                                                   const float* __restrict__ Wh,
                                                   const float* __restrict__ Wl,
                                                   const float* __restrict__ bo,
                                                   float* __restrict__ out)
{
    extern __shared__ __align__(16) char gsm[];
    const int tid = threadIdx.x, lane = tid & 31, wid = tid >> 5;
    const int g = lane >> 2, tg = lane & 3;
    const int m0 = blockIdx.x * 128, n0 = blockIdx.y * 64;

    auto stage = [&](int slot, int kc) {
        #pragma unroll
        for (int i = 0; i < 4; i++) {
            int idx = i * 256 + tid, row = idx >> 3, ch = idx & 7;
            cp16(gsm + GA_OFF + slot * 18432 + row * 144 + ch * 16,
                 A + (size_t)(m0 + row) * 256 + kc + ch * 4);
        }
        #pragma unroll
        for (int i = 0; i < 2; i++) {
            int idx = i * 256 + tid, row = idx >> 3, ch = idx & 7;
            cp16(gsm + GWH_OFF + slot * 9216 + row * 144 + ch * 16,
                 Wh + (size_t)(n0 + row) * 256 + kc + ch * 4);
            cp16(gsm + GWL_OFF + slot * 9216 + row * 144 + ch * 16,
                 Wl + (size_t)(n0 + row) * 256 + kc + ch * 4);
        }
    };

    // ldmatrix per-lane address invariants (proven R14 patterns)
    const uint32_t sb = smem_u32(gsm);
    const int r7 = lane & 7, h8 = (lane >> 3) & 1, hi16 = lane >> 4;
    const uint32_t inv_b = r7 * 144 + h8 * 16 + hi16 * 1152;   // B-frags (W)
    const uint32_t inv_a = r7 * 144 + h8 * 1152 + hi16 * 16;   // A-frags

    float c[8][4];
    #pragma unroll
    for (int nb = 0; nb < 8; nb++)
        #pragma unroll
        for (int j = 0; j < 4; j++) c[nb][j] = 0.f;

    stage(0, 0);
    cp_commit();

    for (int ch = 0; ch < 8; ch++) {
        const int slot = ch & 1;
        if (ch < 7) stage(slot ^ 1, (ch + 1) * 32);
        cp_commit();
        cp_wait1();
        __syncthreads();

        const uint32_t aA  = sb + GA_OFF  + slot * 18432 + wid * 2304 + inv_a;
        const uint32_t aWh = sb + GWH_OFF + slot * 9216 + inv_b;
        const uint32_t aWl = sb + GWL_OFF + slot * 9216 + inv_b;

        #pragma unroll
        for (int kk = 0; kk < 4; kk++) {
            uint32_t ar[4], ah[4], al[4];
            ldsm4(ar, aA + kk * 32);
            #pragma unroll
            for (int r = 0; r < 4; r++) {
                float f = __uint_as_float(ar[r]);
                float fh = tf32_rna_f(f);
                ah[r] = __float_as_uint(fh);
                al[r] = tf32_rna_u(f - fh);
            }
            uint32_t bf[16];
            ldsm4(bf,      aWh + kk * 32);
            ldsm4(bf + 4,  aWh + kk * 32 + 2304);
            ldsm4(bf + 8,  aWh + kk * 32 + 4608);
            ldsm4(bf + 12, aWh + kk * 32 + 6912);
            #pragma unroll
            for (int nb = 0; nb < 8; nb++) {
                mma_tf32(c[nb], ah, bf[2 * nb], bf[2 * nb + 1]);
                mma_tf32(c[nb], al, bf[2 * nb], bf[2 * nb + 1]);
            }
            ldsm4(bf,      aWl + kk * 32);
            ldsm4(bf + 4,  aWl + kk * 32 + 2304);
            ldsm4(bf + 8,  aWl + kk * 32 + 4608);
            ldsm4(bf + 12, aWl + kk * 32 + 6912);
            #pragma unroll
            for (int nb = 0; nb < 8; nb++)
                mma_tf32(c[nb], ah, bf[2 * nb], bf[2 * nb + 1]);
        }
        __syncthreads();
    }

    // epilogue: element (nb,j) -> m = m0+wid*16+g+(j>>1)*8, n = n0+nb*8+2*tg+(j&1)
    #pragma unroll
    for (int nb = 0; nb < 8; nb++) {
        #pragma unroll
        for (int j = 0; j < 4; j++) {
            float v = c[nb][j];
            int m = m0 + wid * 16 + g + (j >> 1) * 8;
            int n = n0 + nb * 8 + 2 * tg + (j & 1);
            if (EPI == 0) {
                int hh = n / 96, rem = n % 96;
                int part = rem >> 5, cd = rem & 31;
                int bb = m >> 11, l = m & 2047;
                int bhx = bb * NH + hh;
                if (part == 0) {
                    g_Q[((size_t)bhx * NL + l) * NHW + cd] =
                        v * 0.17677669529663687f;
                } else if (part == 1) {
                    float h0 = tf32_rna_f(v);
                    size_t base = ((size_t)bhx * NL + l) * NHW + cd;
                    g_K  [base] = h0;
                    g_Klo[base] = tf32_rna_f(v - h0);
                } else {
                    g_Vt[((size_t)bhx * NHW + cd) * NL + l] = tf32_rna_f(v);
                }
            } else {
                out[(size_t)m * NE + n] = v + bo[n];
            }
        }
    }
}

// ---------------------------------------------------------------------------
// bias transpose: [b][q][k][h] fp32 -> [b][h][q][k] fp16 (HBM-bound)
// ---------------------------------------------------------------------------
__global__ __launch_bounds__(256) void bias_t(const float* __restrict__ bias)
{
    size_t idx = (size_t)blockIdx.x * 256 + threadIdx.x;   // over NB*NL*(NL/2)
    int k2 = idx & 1023;
    size_t rest = idx >> 10;
    int q = rest & 2047;
    int b = (int)(rest >> 11);
    const float4* src = (const float4*)(bias + (((size_t)(b * NL + q)) * NL + 2 * k2) * NH);
    float4 a0 = src[0], a1 = src[1], a2 = src[2], a3 = src[3];
    float f[16];
    *(float4*)&f[0]  = a0; *(float4*)&f[4]  = a1;
    *(float4*)&f[8]  = a2; *(float4*)&f[12] = a3;
    #pragma unroll
    for (int h = 0; h < NH; h++)
        g_Bt[((size_t)(b * NH + h) * NL + q) * (NL / 2) + k2] =
            __floats2half2_rn(f[h], f[8 + h]);
}

// ---------------------------------------------------------------------------
// Split-precision tf32 mma.sync attention (R14 structure), V single-MMA.
// CTA = (b,h,128q), 8 warps x 16q, k-tile 32, 2-stage cp.async, 2 CTAs/SM.
// ---------------------------------------------------------------------------
#define QS_OFF  0          // 128 x 144B = 18432
#define KH_OFF  18432      // 2 stages x 4608
#define KL_OFF  27648
#define VH_OFF  36864
#define B_OFF   46080      // 2 stages x 10240 = 20480
#define P_OFF   66560      // 8 warps x 16 x 144B = 18432
#define SM_TOT  84992
#define B_PITCH 40         // halves per bias row (80 bytes)

__global__ __launch_bounds__(256, 2) void attn_mma()
{
    extern __shared__ __align__(16) char smem[];
    const int tid = threadIdx.x, lane = tid & 31, wid = tid >> 5;
    const int g = lane >> 2, tg = lane & 3;
    const int q0 = blockIdx.x * 128;
    const int bh = blockIdx.y;
    const int b  = bh >> 3, h = bh & 7;

    const __half* btp = (const __half*)g_Bt;

    const int krow = tid >> 3, kch = tid & 7;
    auto stage = [&](int s, int k0) {
        cp16(smem + KH_OFF + s * 4608 + krow * 144 + kch * 16,
             g_K   + ((size_t)bh * NL + k0 + krow) * NHW + kch * 4);
        cp16(smem + KL_OFF + s * 4608 + krow * 144 + kch * 16,
             g_Klo + ((size_t)bh * NL + k0 + krow) * NHW + kch * 4);
        cp16(smem + VH_OFF + s * 4608 + krow * 144 + kch * 16,
             g_Vt  + ((size_t)bh * NHW + krow) * NL + k0 + kch * 4);
        #pragma unroll
        for (int i = 0; i < 2; i++) {
            int idx = i * 256 + tid, row = idx >> 2, ch = idx & 3;
            cp16(smem + B_OFF + s * 10240 + row * 80 + ch * 16,
                 btp + ((size_t)bh * NL + q0 + row) * NL + k0 + ch * 8);
        }
    };

    // stage Q (once) + tile 0
    #pragma unroll
    for (int i = 0; i < 4; i++) {
        int idx = i * 256 + tid, row = idx >> 3, ch = idx & 7;
        cp16(smem + QS_OFF + row * 144 + ch * 16,
             g_Q + ((size_t)bh * NL + q0 + row) * NHW + ch * 4);
    }
    stage(0, 0);
    cp_commit();
    cp_wait0();
    __syncthreads();

    // preload split Q fragments (A: m16k8 tf32) for this warp's 16 q-rows
    uint32_t aqh[4][4], aql[4][4];
    {
        const float* qb = (const float*)(smem + QS_OFF) + (wid * 16 + g) * 36;
        #pragma unroll
        for (int kk = 0; kk < 4; kk++) {
            float q00 = qb[kk * 8 + tg];
            float q01 = qb[8 * 36 + kk * 8 + tg];
            float q10 = qb[kk * 8 + tg + 4];
            float q11 = qb[8 * 36 + kk * 8 + tg + 4];
            float h00 = tf32_rna_f(q00), h01 = tf32_rna_f(q01);
            float h10 = tf32_rna_f(q10), h11 = tf32_rna_f(q11);
            aqh[kk][0] = __float_as_uint(h00);
            aqh[kk][1] = __float_as_uint(h01);
            aqh[kk][2] = __float_as_uint(h10);
            aqh[kk][3] = __float_as_uint(h11);
            aql[kk][0] = tf32_rna_u(q00 - h00);
            aql[kk][1] = tf32_rna_u(q01 - h01);
            aql[kk][2] = tf32_rna_u(q10 - h10);
            aql[kk][3] = tf32_rna_u(q11 - h11);
        }
    }

    // ldmatrix per-lane address invariants
    const uint32_t sb = smem_u32(smem);
    const int r7 = lane & 7, h8 = (lane >> 3) & 1, hi16 = lane >> 4;
    const uint32_t inv_b = r7 * 144 + h8 * 16 + hi16 * 1152;   // B-frags (K/V)
    const uint32_t inv_a = r7 * 144 + h8 * 1152 + hi16 * 16;   // A-frags (P)
    const uint32_t aKH = sb + KH_OFF + inv_b;
    const uint32_t aKL = sb + KL_OFF + inv_b;
    const uint32_t aVH = sb + VH_OFF + inv_b;
    const uint32_t aP  = sb + P_OFF + wid * 2304 + inv_a;

    float co[4][4];
    #pragma unroll
    for (int n = 0; n < 4; n++)
        #pragma unroll
        for (int j = 0; j < 4; j++) co[n][j] = 0.f;
    float lsum0 = 0.f, lsum1 = 0.f;

    float* Ps = (float*)(smem + P_OFF) + wid * 16 * 36;

    for (int t = 0; t < 64; t++) {
        const int s = t & 1;
        if (t < 63) stage(s ^ 1, (t + 1) * 32);
        cp_commit();
        cp_wait1();
        __syncthreads();
        const uint32_t so = s * 4608;

        // ---- S = Q @ K^T, split-precision 3-MMA
        float c[4][4];
        #pragma unroll
        for (int n = 0; n < 4; n++)
            #pragma unroll
            for (int j = 0; j < 4; j++) c[n][j] = 0.f;
        #pragma unroll
        for (int kk = 0; kk < 4; kk++) {
            uint32_t bhf[8], blf[8];
            ldsm4(bhf,     aKH + so + kk * 32);
            ldsm4(bhf + 4, aKH + so + kk * 32 + 2304);
            ldsm4(blf,     aKL + so + kk * 32);
            ldsm4(blf + 4, aKL + so + kk * 32 + 2304);
            #pragma unroll
            for (int n = 0; n < 4; n++) {
                mma_tf32(c[n], aqh[kk], bhf[2 * n], bhf[2 * n + 1]);
                mma_tf32(c[n], aql[kk], bhf[2 * n], bhf[2 * n + 1]);
                mma_tf32(c[n], aqh[kk], blf[2 * n], blf[2 * n + 1]);
            }
        }

        // ---- softmax (no max subtraction; scores bounded), P rounded rna
        const __half* brow = (const __half*)(smem + B_OFF + s * 10240)
                           + (wid * 16 + g) * B_PITCH;
        #pragma unroll
        for (int n = 0; n < 4; n++) {
            float2 f0 = __half22float2(*(const __half2*)(brow + n * 8 + 2 * tg));
            float2 f1 = __half22float2(*(const __half2*)(brow + 8 * B_PITCH + n * 8 + 2 * tg));
            float p0 = __uint_as_float(tf32_rna_u(__expf(c[n][0] + f0.x)));
            float p1 = __uint_as_float(tf32_rna_u(__expf(c[n][1] + f0.y)));
            float p2 = __uint_as_float(tf32_rna_u(__expf(c[n][2] + f1.x)));
            float p3 = __uint_as_float(tf32_rna_u(__expf(c[n][3] + f1.y)));
            lsum0 += p0 + p1; lsum1 += p2 + p3;
            *(float2*)(Ps + g * 36 + n * 8 + 2 * tg)       = make_float2(p0, p1);
            *(float2*)(Ps + (g + 8) * 36 + n * 8 + 2 * tg) = make_float2(p2, p3);
        }
        __syncwarp();

        // ---- O += P @ V  (V rna tf32, single MMA)
        #pragma unroll
        for (int kk = 0; kk < 4; kk++) {
            uint32_t pa[4], vhf[8];
            ldsm4(pa, aP + kk * 32);
            ldsm4(vhf,     aVH + so + kk * 32);
            ldsm4(vhf + 4, aVH + so + kk * 32 + 2304);
            #pragma unroll
            for (int n = 0; n < 4; n++)
                mma_tf32(co[n], pa, vhf[2 * n], vhf[2 * n + 1]);
        }
        __syncthreads();
    }

    // ---- epilogue: row sums live on 4 lanes (same g, tg=0..3) -> 2 shuffles
    #pragma unroll
    for (int off = 1; off <= 2; off <<= 1) {
        lsum0 += __shfl_xor_sync(0xffffffffu, lsum0, off);
        lsum1 += __shfl_xor_sync(0xffffffffu, lsum1, off);
    }
    float inv0 = 1.0f / lsum0, inv1 = 1.0f / lsum1;
    int q = q0 + wid * 16 + g;
    float* y0 = g_Y + ((size_t)(b * NL + q)) * NE + h * NHW;
    #pragma unroll
    for (int n = 0; n < 4; n++) {
        *(float2*)(y0 + n * 8 + 2 * tg) =
            make_float2(co[n][0] * inv0, co[n][1] * inv0);
        *(float2*)(y0 + 8 * NE + n * 8 + 2 * tg) =
            make_float2(co[n][2] * inv1, co[n][3] * inv1);
    }
}

// ---------------------------------------------------------------------------
extern "C" void kernel_launch(void* const* d_in, const int* in_sizes, int n_in,
                              void* d_out, int out_size)
{
    const float* x    = (const float*)d_in[0];
    const float* bias = (const float*)d_in[1];
    const float* Wp   = (const float*)d_in[2];
    const float* Wo   = (const float*)d_in[3];
    const float* bo   = (const float*)d_in[4];
    float* out = (float*)d_out;

    float* yptr;  cudaGetSymbolAddress((void**)&yptr, g_Y);
    float* wph;   cudaGetSymbolAddress((void**)&wph, g_Wph);
    float* wpl;   cudaGetSymbolAddress((void**)&wpl, g_Wpl);
    float* woh;   cudaGetSymbolAddress((void**)&woh, g_Woh);
    float* wol;   cudaGetSymbolAddress((void**)&wol, g_Wol);

    cudaFuncSetAttribute(attn_mma, cudaFuncAttributeMaxDynamicSharedMemorySize,
                         SM_TOT);
    cudaFuncSetAttribute(gemm_mma<0>, cudaFuncAttributeMaxDynamicSharedMemorySize,
                         GSM_BYTES);
    cudaFuncSetAttribute(gemm_mma<1>, cudaFuncAttributeMaxDynamicSharedMemorySize,
                         GSM_BYTES);

    split_w<<<1024, 256>>>(Wp, Wo);
    gemm_mma<0><<<dim3(32, 12), 256, GSM_BYTES>>>(x, wph, wpl, nullptr, nullptr);
    bias_t<<<(NB * NL * (NL / 2)) / 256, 256>>>(bias);
    attn_mma<<<dim3(NL / 128, NB * NH), 256, SM_TOT>>>();
    gemm_mma<1><<<dim3(32, 4), 256, GSM_BYTES>>>(yptr, woh, wol, bo, out);
}

// round 17
// speedup vs baseline: 1.2459x; 1.0299x over previous
#include <cuda_runtime.h>
#include <cuda_fp16.h>
#include <cstdint>

#define NL  2048
#define NE  256
#define NH  8
#define NHW 32
#define NB  2

// Scratch (static device globals -- no runtime allocation)
__device__ float   g_Q   [NB*NH*NL*NHW];   // [bh][l][d] fp32 (pre-scaled)
__device__ float   g_K   [NB*NH*NL*NHW];   // [bh][l][d] tf32-hi
__device__ float   g_Klo [NB*NH*NL*NHW];   // [bh][l][d] tf32-lo
__device__ float   g_Vt  [NB*NH*NHW*NL];   // [bh][d][l] tf32 (rna)
__device__ float   g_Y   [NB*NL*NE];
__device__ __half2 g_Bt  [(size_t)NB*NH*NL*NL/2]; // bias^T [b][h][q][k] fp16
__device__ float   g_Wph [768*256];        // W_proj tf32-hi
__device__ float   g_Wpl [768*256];        // W_proj tf32-lo
__device__ float   g_Woh [256*256];        // W_o tf32-hi
__device__ float   g_Wol [256*256];        // W_o tf32-lo

typedef unsigned long long u64;

static __device__ __forceinline__ void cp16(void* dst, const void* src) {
    unsigned d = (unsigned)__cvta_generic_to_shared(dst);
    asm volatile("cp.async.cg.shared.global [%0], [%1], 16;" :: "r"(d), "l"(src));
}
static __device__ __forceinline__ void cp_commit() {
    asm volatile("cp.async.commit_group;");
}
static __device__ __forceinline__ void cp_wait1() {
    asm volatile("cp.async.wait_group 1;");
}
static __device__ __forceinline__ void cp_wait0() {
    asm volatile("cp.async.wait_group 0;");
}
static __device__ __forceinline__ uint32_t smem_u32(const void* p) {
    return (uint32_t)__cvta_generic_to_shared(p);
}
static __device__ __forceinline__ uint32_t tf32_rna_u(float x) {
    uint32_t r; asm("cvt.rna.tf32.f32 %0, %1;" : "=r"(r) : "f"(x)); return r;
}
static __device__ __forceinline__ float tf32_rna_f(float x) {
    return __uint_as_float(tf32_rna_u(x));
}
// tf32 mma m16n8k8, fp32 accumulate (arch-portable tensor path)
static __device__ __forceinline__ void mma_tf32(float* c, const uint32_t* a,
                                                uint32_t b0, uint32_t b1) {
    asm volatile(
        "mma.sync.aligned.m16n8k8.row.col.f32.tf32.tf32.f32 "
        "{%0,%1,%2,%3}, {%4,%5,%6,%7}, {%8,%9}, {%0,%1,%2,%3};"
        : "+f"(c[0]), "+f"(c[1]), "+f"(c[2]), "+f"(c[3])
        : "r"(a[0]), "r"(a[1]), "r"(a[2]), "r"(a[3]), "r"(b0), "r"(b1));
}
// ldmatrix x4 (b16 view of b32 tiles)
static __device__ __forceinline__ void ldsm4(uint32_t* r, uint32_t addr) {
    asm volatile("ldmatrix.sync.aligned.m8n8.x4.shared.b16 {%0,%1,%2,%3}, [%4];"
        : "=r"(r[0]), "=r"(r[1]), "=r"(r[2]), "=r"(r[3]) : "r"(addr));
}

// ---------------------------------------------------------------------------
// W pre-split: Wp (768x256) and Wo (256x256) -> tf32 hi/lo pairs in gmem
// ---------------------------------------------------------------------------
__global__ __launch_bounds__(256) void split_w(const float* __restrict__ Wp,
                                               const float* __restrict__ Wo)
{
    int idx = blockIdx.x * 256 + threadIdx.x;      // over 1024*256
    if (idx < 768 * 256) {
        float v = Wp[idx];
        float h = tf32_rna_f(v);
        g_Wph[idx] = h;
        g_Wpl[idx] = tf32_rna_f(v - h);
    } else {
        int j = idx - 768 * 256;
        float v = Wo[j];
        float h = tf32_rna_f(v);
        g_Woh[j] = h;
        g_Wol[j] = tf32_rna_f(v - h);
    }
}

// ---------------------------------------------------------------------------
// Tensor-core GEMM (NT): C[m][n] = sum_k A[m][k]*W[n][k], K=256.
// 128m x 64n CTA tile, 8 warps x 16m. Split-precision 3-MMA. 2-stage cp.async.
// EPI 0: scatter Q (scaled fp32) / K hi,lo / Vt (rna).  EPI 1: out + bias.
// ---------------------------------------------------------------------------
#define GA_OFF  0
#define GWH_OFF 36864
#define GWL_OFF 55296
#define GSM_BYTES 73728

template<int EPI>
__global__ __launch_bounds__(256, 2) void gemm_mma(const float* __restrict__ A,
                                                   const float* __restrict__ Wh,
                                                   const float* __restrict__ Wl,
                                                   const float* __restrict__ bo,
                                                   float* __restrict__ out)
{
    extern __shared__ __align__(16) char gsm[];
    const int tid = threadIdx.x, lane = tid & 31, wid = tid >> 5;
    const int g = lane >> 2, tg = lane & 3;
    const int m0 = blockIdx.x * 128, n0 = blockIdx.y * 64;

    auto stage = [&](int slot, int kc) {
        #pragma unroll
        for (int i = 0; i < 4; i++) {
            int idx = i * 256 + tid, row = idx >> 3, ch = idx & 7;
            cp16(gsm + GA_OFF + slot * 18432 + row * 144 + ch * 16,
                 A + (size_t)(m0 + row) * 256 + kc + ch * 4);
        }
        #pragma unroll
        for (int i = 0; i < 2; i++) {
            int idx = i * 256 + tid, row = idx >> 3, ch = idx & 7;
            cp16(gsm + GWH_OFF + slot * 9216 + row * 144 + ch * 16,
                 Wh + (size_t)(n0 + row) * 256 + kc + ch * 4);
            cp16(gsm + GWL_OFF + slot * 9216 + row * 144 + ch * 16,
                 Wl + (size_t)(n0 + row) * 256 + kc + ch * 4);
        }
    };

    const uint32_t sb = smem_u32(gsm);
    const int r7 = lane & 7, h8 = (lane >> 3) & 1, hi16 = lane >> 4;
    const uint32_t inv_b = r7 * 144 + h8 * 16 + hi16 * 1152;   // B-frags (W)
    const uint32_t inv_a = r7 * 144 + h8 * 1152 + hi16 * 16;   // A-frags

    float c[8][4];
    #pragma unroll
    for (int nb = 0; nb < 8; nb++)
        #pragma unroll
        for (int j = 0; j < 4; j++) c[nb][j] = 0.f;

    stage(0, 0);
    cp_commit();

    for (int ch = 0; ch < 8; ch++) {
        const int slot = ch & 1;
        if (ch < 7) stage(slot ^ 1, (ch + 1) * 32);
        cp_commit();
        cp_wait1();
        __syncthreads();

        const uint32_t aA  = sb + GA_OFF  + slot * 18432 + wid * 2304 + inv_a;
        const uint32_t aWh = sb + GWH_OFF + slot * 9216 + inv_b;
        const uint32_t aWl = sb + GWL_OFF + slot * 9216 + inv_b;

        #pragma unroll
        for (int kk = 0; kk < 4; kk++) {
            uint32_t ar[4], ah[4], al[4];
            ldsm4(ar, aA + kk * 32);
            #pragma unroll
            for (int r = 0; r < 4; r++) {
                float f = __uint_as_float(ar[r]);
                float fh = tf32_rna_f(f);
                ah[r] = __float_as_uint(fh);
                al[r] = tf32_rna_u(f - fh);
            }
            uint32_t bf[16];
            ldsm4(bf,      aWh + kk * 32);
            ldsm4(bf + 4,  aWh + kk * 32 + 2304);
            ldsm4(bf + 8,  aWh + kk * 32 + 4608);
            ldsm4(bf + 12, aWh + kk * 32 + 6912);
            #pragma unroll
            for (int nb = 0; nb < 8; nb++) {
                mma_tf32(c[nb], ah, bf[2 * nb], bf[2 * nb + 1]);
                mma_tf32(c[nb], al, bf[2 * nb], bf[2 * nb + 1]);
            }
            ldsm4(bf,      aWl + kk * 32);
            ldsm4(bf + 4,  aWl + kk * 32 + 2304);
            ldsm4(bf + 8,  aWl + kk * 32 + 4608);
            ldsm4(bf + 12, aWl + kk * 32 + 6912);
            #pragma unroll
            for (int nb = 0; nb < 8; nb++)
                mma_tf32(c[nb], ah, bf[2 * nb], bf[2 * nb + 1]);
        }
        __syncthreads();
    }

    #pragma unroll
    for (int nb = 0; nb < 8; nb++) {
        #pragma unroll
        for (int j = 0; j < 4; j++) {
            float v = c[nb][j];
            int m = m0 + wid * 16 + g + (j >> 1) * 8;
            int n = n0 + nb * 8 + 2 * tg + (j & 1);
            if (EPI == 0) {
                int hh = n / 96, rem = n % 96;
                int part = rem >> 5, cd = rem & 31;
                int bb = m >> 11, l = m & 2047;
                int bhx = bb * NH + hh;
                if (part == 0) {
                    g_Q[((size_t)bhx * NL + l) * NHW + cd] =
                        v * 0.17677669529663687f;
                } else if (part == 1) {
                    float h0 = tf32_rna_f(v);
                    size_t base = ((size_t)bhx * NL + l) * NHW + cd;
                    g_K  [base] = h0;
                    g_Klo[base] = tf32_rna_f(v - h0);
                } else {
                    g_Vt[((size_t)bhx * NHW + cd) * NL + l] = tf32_rna_f(v);
                }
            } else {
                out[(size_t)m * NE + n] = v + bo[n];
            }
        }
    }
}

// ---------------------------------------------------------------------------
// bias transpose: [b][q][k][h] fp32 -> [b][h][q][k] fp16 (HBM-bound)
// ---------------------------------------------------------------------------
__global__ __launch_bounds__(256) void bias_t(const float* __restrict__ bias)
{
    size_t idx = (size_t)blockIdx.x * 256 + threadIdx.x;   // over NB*NL*(NL/2)
    int k2 = idx & 1023;
    size_t rest = idx >> 10;
    int q = rest & 2047;
    int b = (int)(rest >> 11);
    const float4* src = (const float4*)(bias + (((size_t)(b * NL + q)) * NL + 2 * k2) * NH);
    float4 a0 = src[0], a1 = src[1], a2 = src[2], a3 = src[3];
    float f[16];
    *(float4*)&f[0]  = a0; *(float4*)&f[4]  = a1;
    *(float4*)&f[8]  = a2; *(float4*)&f[12] = a3;
    #pragma unroll
    for (int h = 0; h < NH; h++)
        g_Bt[((size_t)(b * NH + h) * NL + q) * (NL / 2) + k2] =
            __floats2half2_rn(f[h], f[8 + h]);
}

// ---------------------------------------------------------------------------
// Split-precision tf32 mma.sync attention, small-CTA regrid:
// CTA = 128 threads (4 warps x 16q = 64q), grid 512 -> 4 CTAs/SM, uniform
// residency. k-tile 32, 2-stage cp.async, P overlaid on dead Q region
// (warp-private ranges coincide). Numerics identical to R16.
// ---------------------------------------------------------------------------
#define QP_OFF  0          // Q (prologue) then P; 64 x 144B = 9216
#define KH_OFF  9216       // 2 stages x 4608
#define KL_OFF  18432
#define VH_OFF  27648
#define B_OFF   36864      // 2 stages x 5120 (64 q-rows x 80B)
#define SM_TOT  47104
#define B_PITCH 40         // halves per bias row (80 bytes)

__global__ __launch_bounds__(128, 4) void attn_mma()
{
    extern __shared__ __align__(16) char smem[];
    const int tid = threadIdx.x, lane = tid & 31, wid = tid >> 5;
    const int g = lane >> 2, tg = lane & 3;
    const int q0 = blockIdx.x * 64;
    const int bh = blockIdx.y;
    const int b  = bh >> 3, h = bh & 7;

    const __half* btp = (const __half*)g_Bt;

    auto stage = [&](int s, int k0) {
        #pragma unroll
        for (int i = 0; i < 2; i++) {
            int idx = i * 128 + tid, row = idx >> 3, ch = idx & 7;
            cp16(smem + KH_OFF + s * 4608 + row * 144 + ch * 16,
                 g_K   + ((size_t)bh * NL + k0 + row) * NHW + ch * 4);
            cp16(smem + KL_OFF + s * 4608 + row * 144 + ch * 16,
                 g_Klo + ((size_t)bh * NL + k0 + row) * NHW + ch * 4);
            cp16(smem + VH_OFF + s * 4608 + row * 144 + ch * 16,
                 g_Vt  + ((size_t)bh * NHW + row) * NL + k0 + ch * 4);
        }
        #pragma unroll
        for (int i = 0; i < 2; i++) {
            int idx = i * 128 + tid, row = idx >> 2, ch = idx & 3;
            cp16(smem + B_OFF + s * 5120 + row * 80 + ch * 16,
                 btp + ((size_t)bh * NL + q0 + row) * NL + k0 + ch * 8);
        }
    };

    // stage Q (once) + tile 0
    #pragma unroll
    for (int i = 0; i < 4; i++) {
        int idx = i * 128 + tid, row = idx >> 3, ch = idx & 7;
        cp16(smem + QP_OFF + row * 144 + ch * 16,
             g_Q + ((size_t)bh * NL + q0 + row) * NHW + ch * 4);
    }
    stage(0, 0);
    cp_commit();
    cp_wait0();
    __syncthreads();

    // preload split Q fragments (A: m16k8 tf32) for this warp's 16 q-rows
    uint32_t aqh[4][4], aql[4][4];
    {
        const float* qb = (const float*)(smem + QP_OFF) + (wid * 16 + g) * 36;
        #pragma unroll
        for (int kk = 0; kk < 4; kk++) {
            float q00 = qb[kk * 8 + tg];
            float q01 = qb[8 * 36 + kk * 8 + tg];
            float q10 = qb[kk * 8 + tg + 4];
            float q11 = qb[8 * 36 + kk * 8 + tg + 4];
            float h00 = tf32_rna_f(q00), h01 = tf32_rna_f(q01);
            float h10 = tf32_rna_f(q10), h11 = tf32_rna_f(q11);
            aqh[kk][0] = __float_as_uint(h00);
            aqh[kk][1] = __float_as_uint(h01);
            aqh[kk][2] = __float_as_uint(h10);
            aqh[kk][3] = __float_as_uint(h11);
            aql[kk][0] = tf32_rna_u(q00 - h00);
            aql[kk][1] = tf32_rna_u(q01 - h01);
            aql[kk][2] = tf32_rna_u(q10 - h10);
            aql[kk][3] = tf32_rna_u(q11 - h11);
        }
    }

    // ldmatrix per-lane address invariants
    const uint32_t sb = smem_u32(smem);
    const int r7 = lane & 7, h8 = (lane >> 3) & 1, hi16 = lane >> 4;
    const uint32_t inv_b = r7 * 144 + h8 * 16 + hi16 * 1152;   // B-frags (K/V)
    const uint32_t inv_a = r7 * 144 + h8 * 1152 + hi16 * 16;   // A-frags (P)
    const uint32_t aKH = sb + KH_OFF + inv_b;
    const uint32_t aKL = sb + KL_OFF + inv_b;
    const uint32_t aVH = sb + VH_OFF + inv_b;
    const uint32_t aP  = sb + QP_OFF + wid * 2304 + inv_a;

    float co[4][4];
    #pragma unroll
    for (int n = 0; n < 4; n++)
        #pragma unroll
        for (int j = 0; j < 4; j++) co[n][j] = 0.f;
    float lsum0 = 0.f, lsum1 = 0.f;

    float* Ps = (float*)(smem + QP_OFF) + wid * 16 * 36;

    for (int t = 0; t < 64; t++) {
        const int s = t & 1;
        if (t < 63) stage(s ^ 1, (t + 1) * 32);
        cp_commit();
        cp_wait1();
        __syncthreads();
        const uint32_t so = s * 4608;

        // ---- S = Q @ K^T, split-precision 3-MMA
        float c[4][4];
        #pragma unroll
        for (int n = 0; n < 4; n++)
            #pragma unroll
            for (int j = 0; j < 4; j++) c[n][j] = 0.f;
        #pragma unroll
        for (int kk = 0; kk < 4; kk++) {
            uint32_t bhf[8], blf[8];
            ldsm4(bhf,     aKH + so + kk * 32);
            ldsm4(bhf + 4, aKH + so + kk * 32 + 2304);
            ldsm4(blf,     aKL + so + kk * 32);
            ldsm4(blf + 4, aKL + so + kk * 32 + 2304);
            #pragma unroll
            for (int n = 0; n < 4; n++) {
                mma_tf32(c[n], aqh[kk], bhf[2 * n], bhf[2 * n + 1]);
                mma_tf32(c[n], aql[kk], bhf[2 * n], bhf[2 * n + 1]);
                mma_tf32(c[n], aqh[kk], blf[2 * n], blf[2 * n + 1]);
            }
        }

        // ---- softmax (no max subtraction; scores bounded), P rounded rna
        const __half* brow = (const __half*)(smem + B_OFF + s * 5120)
                           + (wid * 16 + g) * B_PITCH;
        #pragma unroll
        for (int n = 0; n < 4; n++) {
            float2 f0 = __half22float2(*(const __half2*)(brow + n * 8 + 2 * tg));
            float2 f1 = __half22float2(*(const __half2*)(brow + 8 * B_PITCH + n * 8 + 2 * tg));
            float p0 = __uint_as_float(tf32_rna_u(__expf(c[n][0] + f0.x)));
            float p1 = __uint_as_float(tf32_rna_u(__expf(c[n][1] + f0.y)));
            float p2 = __uint_as_float(tf32_rna_u(__expf(c[n][2] + f1.x)));
            float p3 = __uint_as_float(tf32_rna_u(__expf(c[n][3] + f1.y)));
            lsum0 += p0 + p1; lsum1 += p2 + p3;
            *(float2*)(Ps + g * 36 + n * 8 + 2 * tg)       = make_float2(p0, p1);
            *(float2*)(Ps + (g + 8) * 36 + n * 8 + 2 * tg) = make_float2(p2, p3);
        }
        __syncwarp();

        // ---- O += P @ V  (V rna tf32, single MMA)
        #pragma unroll
        for (int kk = 0; kk < 4; kk++) {
            uint32_t pa[4], vhf[8];
            ldsm4(pa, aP + kk * 32);
            ldsm4(vhf,     aVH + so + kk * 32);
            ldsm4(vhf + 4, aVH + so + kk * 32 + 2304);
            #pragma unroll
            for (int n = 0; n < 4; n++)
                mma_tf32(co[n], pa, vhf[2 * n], vhf[2 * n + 1]);
        }
        __syncthreads();
    }

    // ---- epilogue: row sums live on 4 lanes (same g, tg=0..3) -> 2 shuffles
    #pragma unroll
    for (int off = 1; off <= 2; off <<= 1) {
        lsum0 += __shfl_xor_sync(0xffffffffu, lsum0, off);
        lsum1 += __shfl_xor_sync(0xffffffffu, lsum1, off);
    }
    float inv0 = 1.0f / lsum0, inv1 = 1.0f / lsum1;
    int q = q0 + wid * 16 + g;
    float* y0 = g_Y + ((size_t)(b * NL + q)) * NE + h * NHW;
    #pragma unroll
    for (int n = 0; n < 4; n++) {
        *(float2*)(y0 + n * 8 + 2 * tg) =
            make_float2(co[n][0] * inv0, co[n][1] * inv0);
        *(float2*)(y0 + 8 * NE + n * 8 + 2 * tg) =
            make_float2(co[n][2] * inv1, co[n][3] * inv1);
    }
}

// ---------------------------------------------------------------------------
extern "C" void kernel_launch(void* const* d_in, const int* in_sizes, int n_in,
                              void* d_out, int out_size)
{
    const float* x    = (const float*)d_in[0];
    const float* bias = (const float*)d_in[1];
    const float* Wp   = (const float*)d_in[2];
    const float* Wo   = (const float*)d_in[3];
    const float* bo   = (const float*)d_in[4];
    float* out = (float*)d_out;

    float* yptr;  cudaGetSymbolAddress((void**)&yptr, g_Y);
    float* wph;   cudaGetSymbolAddress((void**)&wph, g_Wph);
    float* wpl;   cudaGetSymbolAddress((void**)&wpl, g_Wpl);
    float* woh;   cudaGetSymbolAddress((void**)&woh, g_Woh);
    float* wol;   cudaGetSymbolAddress((void**)&wol, g_Wol);

    cudaFuncSetAttribute(attn_mma, cudaFuncAttributeMaxDynamicSharedMemorySize,
                         SM_TOT);
    cudaFuncSetAttribute(gemm_mma<0>, cudaFuncAttributeMaxDynamicSharedMemorySize,
                         GSM_BYTES);
    cudaFuncSetAttribute(gemm_mma<1>, cudaFuncAttributeMaxDynamicSharedMemorySize,
                         GSM_BYTES);

    split_w<<<1024, 256>>>(Wp, Wo);
    gemm_mma<0><<<dim3(32, 12), 256, GSM_BYTES>>>(x, wph, wpl, nullptr, nullptr);
    bias_t<<<(NB * NL * (NL / 2)) / 256, 256>>>(bias);
    attn_mma<<<dim3(NL / 64, NB * NH), 128, SM_TOT>>>();
    gemm_mma<1><<<dim3(32, 4), 256, GSM_BYTES>>>(yptr, woh, wol, bo, out);
}